// round 15
// baseline (speedup 1.0000x reference)
#include <cuda_runtime.h>

#define NN    50000
#define DD    128
#define EE    600000
#define NPRED 200000
#define NSEL  300000
#define UD    256
#define NB    49          // scan blocks: 49*1024 >= NN
#define NSM   148
#define NT64  ((NN + 63) / 64)   // 782 row-tiles

typedef unsigned long long ull;

// packed f32x2 helpers (sm_103a FFMA2 — only reachable via PTX)
#define FMA2(d, a, b) asm("fma.rn.f32x2 %0, %1, %2, %0;" : "+l"(d) : "l"(a), "l"(b))
#define UNPACK2(lo, hi, s) asm("mov.b64 {%0, %1}, %2;" : "=f"(lo), "=f"(hi) : "l"(s))

// ---------------- scratch (device globals: allocation-free) ----------------
__device__ int   g_deg_in[NN];
__device__ int   g_deg_out[NN];
__device__ float g_rin[NN];
__device__ float g_rout[NN];
__device__ int   g_off[NN + 1];
__device__ int   g_cur[NN];
__device__ int   g_srcs[EE];
__device__ int   g_bsum[NB];
__device__ float g_Wc[DD * DD];           // W1 @ W2
__device__ float g_c1[DD];                // b1 @ W2
__device__ float g_srin[NN];              // rin[i] * sum_{s in in(i)} rout[s]
__device__ float g_bufA[(size_t)NN * DD];
__device__ float g_bufB[(size_t)NN * DD];
__device__ float g_part[(size_t)NN * 4];  // [node][half*2 + {p0,p1}]

// grid-barrier state (zero-initialized; gen monotonic across replays)
__device__ unsigned g_cnt = 0;
__device__ unsigned g_gen = 0;

__device__ __forceinline__ void gridbar() {
    __syncthreads();
    if (threadIdx.x == 0) {
        __threadfence();
        unsigned gen = atomicAdd(&g_gen, 0u);
        if (atomicAdd(&g_cnt, 1u) == NSM - 1) {
            atomicExch(&g_cnt, 0u);     // reset BEFORE release
            __threadfence();
            atomicAdd(&g_gen, 1u);
        } else {
            while (atomicAdd(&g_gen, 0u) == gen) { }
        }
        __threadfence();
    }
    __syncthreads();
}

// ---------------- fused preprocessing: one persistent kernel -----------------
// phases: [zero + Wc=W1@W2,c1=b1@W2] | [degree count] | [rsqrt + block scan]
//         | [scan combine] | [CSR fill]
__global__ void __launch_bounds__(1024, 1)
k_pre(const int* __restrict__ ei, const float* __restrict__ W1,
      const float* __restrict__ W2, const float* __restrict__ b1) {
    __shared__ int wsum[32];
    __shared__ int s_pre;
    int tid = threadIdx.x;
    int b   = blockIdx.x;
    int gt  = b * 1024 + tid;
    const int GSZ = NSM * 1024;

    // ---- phase 0: zero degrees + combined weights ----
    for (int i = gt; i < NN; i += GSZ) { g_deg_in[i] = 0; g_deg_out[i] = 0; }
    if (gt < DD * DD + DD) {
        int row = gt >> 7, col = gt & 127;
        const float* a = (gt < DD * DD) ? (W1 + row * DD) : b1;
        float acc = 0.f;
        #pragma unroll 8
        for (int k = 0; k < DD; k++)
            acc = fmaf(a[k], W2[k * DD + col], acc);
        if (gt < DD * DD) g_Wc[gt] = acc;
        else              g_c1[col] = acc;
    }
    gridbar();

    // ---- phase 1: degree count ----
    for (int e = gt; e < EE; e += GSZ) {
        atomicAdd(&g_deg_out[ei[e]], 1);
        atomicAdd(&g_deg_in[ei[EE + e]], 1);
    }
    gridbar();

    // ---- phase 2a: rsqrt + per-block exclusive scan (blocks 0..NB-1) ----
    if (b < NB) {
        int i    = b * 1024 + tid;
        int lane = tid & 31, wid = tid >> 5;
        int v = (i < NN) ? __ldcg(&g_deg_in[i]) : 0;

        if (i < NN) {
            int dout = __ldcg(&g_deg_out[i]); if (dout < 1) dout = 1;
            int din  = v;                     if (din  < 1) din  = 1;
            g_rout[i] = rsqrtf((float)dout);
            g_rin[i]  = rsqrtf((float)din);
        }

        int x = v;
        #pragma unroll
        for (int s = 1; s < 32; s <<= 1) {
            int t = __shfl_up_sync(0xffffffffu, x, s);
            if (lane >= s) x += t;
        }
        if (lane == 31) wsum[wid] = x;
        __syncthreads();
        if (wid == 0) {
            int y = wsum[lane];
            #pragma unroll
            for (int s = 1; s < 32; s <<= 1) {
                int t = __shfl_up_sync(0xffffffffu, y, s);
                if (lane >= s) y += t;
            }
            wsum[lane] = y;
        }
        __syncthreads();

        int excl = x - v + (wid ? wsum[wid - 1] : 0);
        if (i < NN) g_off[i] = excl;
        if (tid == 1023) g_bsum[b] = excl + v;
    }
    gridbar();

    // ---- phase 2b: add block prefixes, init g_cur ----
    if (b < NB) {
        if (tid == 0) {
            int run = 0;
            #pragma unroll
            for (int q = 0; q < NB; q++) {
                int t = __ldcg(&g_bsum[q]);
                if (q == b) s_pre = run;
                run += t;
            }
            if (b == 0) g_off[NN] = run;
        }
        __syncthreads();
        int i = b * 1024 + tid;
        if (i < NN) {
            int o = __ldcg(&g_off[i]) + s_pre;
            g_off[i] = o;
            g_cur[i] = o;
        }
    }
    gridbar();

    // ---- phase 3: CSR fill ----
    for (int e = gt; e < EE; e += GSZ) {
        int d = ei[EE + e];
        int slot = atomicAdd(&g_cur[d], 1);
        g_srcs[slot] = ei[e];
    }
}

// ---------------- aggA: bufA[i] = rout[i]*rin[i] * sum rout[s]*X[s] ----------
__global__ void k_aggA(const float* __restrict__ X) {
    int t = blockIdx.x * blockDim.x + threadIdx.x;
    int w = t >> 5, lane = t & 31;
    if (w >= NN) return;
    int lo = g_off[w], hi = g_off[w + 1];
    float4 acc = make_float4(0.f, 0.f, 0.f, 0.f);
    for (int j = lo; j < hi; j++) {
        int s = g_srcs[j];
        float r = g_rout[s];
        float4 v = *(const float4*)(X + (size_t)s * DD + lane * 4);
        acc.x = fmaf(r, v.x, acc.x);
        acc.y = fmaf(r, v.y, acc.y);
        acc.z = fmaf(r, v.z, acc.z);
        acc.w = fmaf(r, v.w, acc.w);
    }
    float sc = g_rout[w] * g_rin[w];
    float4 o;
    o.x = acc.x * sc; o.y = acc.y * sc; o.z = acc.z * sc; o.w = acc.w * sc;
    *(float4*)(g_bufA + (size_t)w * DD + lane * 4) = o;
}

// ---------------- aggB: bufB[i] = sum bufA[s] ; srin[i] = rin[i]*sum rout[s] --
__global__ void k_aggB() {
    int t = blockIdx.x * blockDim.x + threadIdx.x;
    int w = t >> 5, lane = t & 31;
    if (w >= NN) return;
    int lo = g_off[w], hi = g_off[w + 1];
    float4 acc = make_float4(0.f, 0.f, 0.f, 0.f);
    float ss = 0.f;
    for (int j = lo; j < hi; j++) {
        int s = g_srcs[j];
        ss += g_rout[s];
        float4 v = *(const float4*)(g_bufA + (size_t)s * DD + lane * 4);
        acc.x += v.x; acc.y += v.y; acc.z += v.z; acc.w += v.w;
    }
    *(float4*)(g_bufB + (size_t)w * DD + lane * 4) = acc;
    if (lane == 0) g_srin[w] = g_rin[w] * ss;
}

// ---------------- conv GEMM (persistent, round-11 mainloop) ------------------
// h2 = rin*(B@Wc) + srin*c1 + b2 ; B rows in bufB, h2 written to bufA.
__global__ void __launch_bounds__(256, 2)
k_conv(const float* __restrict__ b2) {
    extern __shared__ float sm[];
    float* Ws2 = sm;              // 64 kp x 128 cols x float2 (64 KB)
    float* Xs  = sm + DD * DD;    // 64 x 128

    int tid = threadIdx.x, wid = tid >> 5, lane = tid & 31;

    {   // stage Wc k-pair interleaved, once
        float2* Wd = (float2*)Ws2;
        #pragma unroll
        for (int q = 0; q < 32; q++) {
            int idx = tid + 256 * q;
            int kp = idx >> 7, c = idx & 127;
            Wd[idx] = make_float2(g_Wc[(2 * kp) * DD + c], g_Wc[(2 * kp + 1) * DD + c]);
        }
    }
    __syncthreads();
    const ull* Wp = (const ull*)Ws2;
    float4 c1v = *(const float4*)(g_c1 + 4 * lane);
    float4 b2v = *(const float4*)(b2 + 4 * lane);

    for (int tile = blockIdx.x; tile < NT64; tile += 2 * NSM) {
        int m0 = tile * 64;
        #pragma unroll
        for (int q = 0; q < 8; q++) {
            int gi = m0 + wid * 8 + q;
            float4 v = make_float4(0.f, 0.f, 0.f, 0.f);
            if (gi < NN)
                v = *(const float4*)(g_bufB + (size_t)gi * DD + 4 * lane);
            *(float4*)(Xs + (wid * 8 + q) * DD + 4 * lane) = v;
        }
        __syncwarp();

        ull acc[8][4];
        #pragma unroll
        for (int r = 0; r < 8; r++)
            #pragma unroll
            for (int c = 0; c < 4; c++) acc[r][c] = 0ull;

        #pragma unroll 8
        for (int kp = 0; kp < DD / 2; kp++) {
            ulonglong2 bb0 = *(const ulonglong2*)(Wp + kp * DD + 4 * lane);
            ulonglong2 bb1 = *(const ulonglong2*)(Wp + kp * DD + 4 * lane + 2);
            ull a2[8];
            #pragma unroll
            for (int r = 0; r < 8; r++)
                a2[r] = *(const ull*)(Xs + (wid * 8 + r) * DD + 2 * kp);  // broadcast
            #pragma unroll
            for (int r = 0; r < 8; r++) {
                FMA2(acc[r][0], a2[r], bb0.x);
                FMA2(acc[r][1], a2[r], bb0.y);
                FMA2(acc[r][2], a2[r], bb1.x);
                FMA2(acc[r][3], a2[r], bb1.y);
            }
        }

        #pragma unroll
        for (int r = 0; r < 8; r++) {
            int gi = m0 + wid * 8 + r;
            if (gi < NN) {
                float ri = g_rin[gi];
                float sr = g_srin[gi];
                float4 o;
                float lo, hi;
                UNPACK2(lo, hi, acc[r][0]); o.x = (lo + hi) * ri + sr * c1v.x + b2v.x;
                UNPACK2(lo, hi, acc[r][1]); o.y = (lo + hi) * ri + sr * c1v.y + b2v.y;
                UNPACK2(lo, hi, acc[r][2]); o.z = (lo + hi) * ri + sr * c1v.z + b2v.z;
                UNPACK2(lo, hi, acc[r][3]); o.w = (lo + hi) * ri + sr * c1v.w + b2v.w;
                *(float4*)(g_bufA + (size_t)gi * DD + 4 * lane) = o;
            }
        }
        __syncwarp();
    }
}

// ---------------- dense head, HALF-SPLIT (reads bufA) ------------------------
__global__ void __launch_bounds__(256, 2)
k_dense(const float* __restrict__ dW,
        const float* __restrict__ db,
        const float* __restrict__ oW) {
    extern __shared__ float sm[];
    float* Ws2  = sm;                  // 64 kp x 128 cols x float2 (64 KB)
    float* Xs   = Ws2 + DD * DD;       // 64 x 128 (32 KB)
    float* s_db = Xs + 64 * DD;        // 128
    float* s_oW = s_db + 128;          // 256

    int tid  = threadIdx.x, wid = tid >> 5, lane = tid & 31;
    int half = blockIdx.x & 1;
    int cbase = half * 128;

    {   // stage this half of dense_W, k-pair interleaved
        float2* Wd = (float2*)Ws2;
        #pragma unroll
        for (int q = 0; q < 32; q++) {
            int idx = tid + 256 * q;          // 0..8191
            int kp = idx >> 7, c = idx & 127;
            Wd[idx] = make_float2(dW[(2 * kp) * UD + cbase + c],
                                  dW[(2 * kp + 1) * UD + cbase + c]);
        }
    }
    if (tid < 128) {
        s_db[tid]         = db[cbase + tid];
        s_oW[tid * 2]     = oW[(cbase + tid) * 2];
        s_oW[tid * 2 + 1] = oW[(cbase + tid) * 2 + 1];
    }
    __syncthreads();
    const ull* Wp = (const ull*)Ws2;

    for (int tile = blockIdx.x >> 1; tile < NT64; tile += NSM) {
        int m0 = tile * 64;
        #pragma unroll
        for (int q = 0; q < 8; q++) {
            int gi = m0 + wid * 8 + q;
            float4 v = make_float4(0.f, 0.f, 0.f, 0.f);
            if (gi < NN)
                v = *(const float4*)(g_bufA + (size_t)gi * DD + 4 * lane);
            *(float4*)(Xs + (wid * 8 + q) * DD + 4 * lane) = v;
        }
        __syncwarp();

        ull acc[8][4];
        #pragma unroll
        for (int r = 0; r < 8; r++)
            #pragma unroll
            for (int c = 0; c < 4; c++) acc[r][c] = 0ull;

        #pragma unroll 8
        for (int kp = 0; kp < DD / 2; kp++) {
            ulonglong2 bb0 = *(const ulonglong2*)(Wp + kp * DD + 4 * lane);
            ulonglong2 bb1 = *(const ulonglong2*)(Wp + kp * DD + 4 * lane + 2);
            ull a2[8];
            #pragma unroll
            for (int r = 0; r < 8; r++)
                a2[r] = *(const ull*)(Xs + (wid * 8 + r) * DD + 2 * kp);  // broadcast
            #pragma unroll
            for (int r = 0; r < 8; r++) {
                FMA2(acc[r][0], a2[r], bb0.x);
                FMA2(acc[r][1], a2[r], bb0.y);
                FMA2(acc[r][2], a2[r], bb1.x);
                FMA2(acc[r][3], a2[r], bb1.y);
            }
        }

        // epilogue: relu + partial 128->2, warp reduce, write g_part
        #pragma unroll
        for (int r = 0; r < 8; r++) {
            float p0 = 0.f, p1 = 0.f;
            #pragma unroll
            for (int c = 0; c < 4; c++) {
                float lo, hi;
                UNPACK2(lo, hi, acc[r][c]);
                int col = 4 * lane + c;               // col within half
                float v = fmaxf(lo + hi + s_db[col], 0.f);
                p0 = fmaf(v, s_oW[col * 2],     p0);
                p1 = fmaf(v, s_oW[col * 2 + 1], p1);
            }
            #pragma unroll
            for (int o = 16; o; o >>= 1) {
                p0 += __shfl_down_sync(0xffffffffu, p0, o);
                p1 += __shfl_down_sync(0xffffffffu, p1, o);
            }
            if (lane == 0) {
                int gi = m0 + wid * 8 + r;
                if (gi < NN)
                    *(float2*)(g_part + (size_t)gi * 4 + half * 2) = make_float2(p0, p1);
            }
        }
        __syncwarp();
    }
}

// ---------------- output: combine halves + ob + softmax + gather -------------
__global__ void k_out(const int* __restrict__ set_idx,
                      const int* __restrict__ oe,
                      const float* __restrict__ ob,
                      float* __restrict__ out) {
    int i = blockIdx.x * blockDim.x + threadIdx.x;
    if (i < NSEL) {
        int node = oe[set_idx[i]];
        float4 pt = *(const float4*)(g_part + (size_t)node * 4);
        float z0 = pt.x + pt.z + ob[0];
        float z1 = pt.y + pt.w + ob[1];
        float m  = fmaxf(z0, z1);
        float e0 = __expf(z0 - m), e1 = __expf(z1 - m);
        float inv = 1.f / (e0 + e1);
        *(float2*)(out + (size_t)i * 2) = make_float2(e0 * inv, e1 * inv);
    }
}

// ---------------- host launch ----------------
extern "C" void kernel_launch(void* const* d_in, const int* in_sizes, int n_in,
                              void* d_out, int out_size) {
    const float* node_state = (const float*)d_in[0];
    const int*   edge_index = (const int*)d_in[1];
    const int*   out_edges  = (const int*)d_in[2];
    const int*   set_idx    = (const int*)d_in[3];
    const float* W1         = (const float*)d_in[4];
    const float* b1         = (const float*)d_in[5];
    const float* W2         = (const float*)d_in[6];
    const float* b2         = (const float*)d_in[7];
    const float* dW         = (const float*)d_in[8];
    const float* db         = (const float*)d_in[9];
    const float* oW         = (const float*)d_in[10];
    const float* ob         = (const float*)d_in[11];
    float* out = (float*)d_out;

    const int GEMM_SMEM  = (DD * DD + 64 * DD) * 4;                // 96 KB
    const int DENSE_SMEM = (DD * DD + 64 * DD + 128 + 256) * 4;    // ~97.5 KB

    cudaFuncSetAttribute(k_conv,  cudaFuncAttributeMaxDynamicSharedMemorySize, GEMM_SMEM);
    cudaFuncSetAttribute(k_dense, cudaFuncAttributeMaxDynamicSharedMemorySize, DENSE_SMEM);

    // single fused preprocessing kernel (persistent, 1 wave, grid barriers)
    k_pre<<<NSM, 1024>>>(edge_index, W1, W2, b1);

    // collapsed conv layers:
    k_aggA<<<(NN * 32 + 255) / 256, 256>>>(node_state);  // bufA = rout*rin*agg(rout*X)
    k_aggB<<<(NN * 32 + 255) / 256, 256>>>();            // bufB = agg(bufA), srin
    k_conv<<<2 * NSM, 256, GEMM_SMEM>>>(b2);             // bufA = h2

    // dense head (half-split) + combine/softmax/gather
    k_dense<<<2 * NSM, 256, DENSE_SMEM>>>(dW, db, oW);
    k_out  <<<(NSEL + 255) / 256, 256>>>(set_idx, out_edges, ob, out);
}

// round 16
// speedup vs baseline: 1.0750x; 1.0750x over previous
#include <cuda_runtime.h>
#include <cuda_bf16.h>
#include <mma.h>

#define NN    50000
#define DD    128
#define EE    600000
#define NPRED 200000
#define NSEL  300000
#define UD    256
#define NB    49
#define NSM   148
#define NT64  ((NN + 63) / 64)   // 782 row-tiles

typedef unsigned long long ull;
using namespace nvcuda;

// ---------------- scratch (device globals: allocation-free) ----------------
__device__ int   g_deg_in[NN];
__device__ int   g_deg_out[NN];
__device__ float g_rin[NN];
__device__ float g_rout[NN];
__device__ int   g_off[NN + 1];
__device__ int   g_cur[NN];
__device__ int   g_srcs[EE];
__device__ int   g_bsum[NB];
__device__ float g_Wc[DD * DD];           // W1 @ W2
__device__ float g_c1[DD];                // b1 @ W2
__device__ float g_srin[NN];
__device__ float g_bufA[(size_t)NN * DD];
__device__ float g_bufB[(size_t)NN * DD];
__device__ float g_part[(size_t)NN * 4];  // [node][half*2 + {p0,p1}]

union BF4 { __nv_bfloat16 b[4]; ull u; };

// smem geometry for the wmma GEMMs (bf16, padded stride 136 elems = 272B)
#define APAD   136
#define A_BYTES (64 * APAD * 2)            // 17408 per buffer
#define B_BYTES (128 * APAD * 2)           // 34816 per buffer
#define GEMM_SMEM_T (2 * A_BYTES + 2 * B_BYTES)   // 104448
#define OPAD   132                          // f32 epilogue scratch stride

// ---------------- combined weights: Wc = W1@W2, c1 = b1@W2 ----------------
__global__ void k_wc(const float* __restrict__ W1, const float* __restrict__ W2,
                     const float* __restrict__ b1) {
    __shared__ float row[DD];
    int b = blockIdx.x;
    int j = threadIdx.x;
    row[j] = (b < DD) ? W1[b * DD + j] : b1[j];
    __syncthreads();
    float acc = 0.f;
    #pragma unroll 8
    for (int k = 0; k < DD; k++)
        acc = fmaf(row[k], W2[k * DD + j], acc);
    if (b < DD) g_Wc[b * DD + j] = acc;
    else        g_c1[j] = acc;
}

// ---------------- degree counting ----------------
__global__ void k_zero() {
    int i = blockIdx.x * blockDim.x + threadIdx.x;
    if (i < NN) { g_deg_in[i] = 0; g_deg_out[i] = 0; }
}

__global__ void k_count(const int* __restrict__ ei) {
    int e = blockIdx.x * blockDim.x + threadIdx.x;
    if (e < EE) {
        atomicAdd(&g_deg_out[ei[e]], 1);
        atomicAdd(&g_deg_in[ei[EE + e]], 1);
    }
}

// ---------------- scan pass A (+ fused rsqrt) ----------------
__global__ void k_scan_a() {
    __shared__ int wsum[32];
    int tid  = threadIdx.x;
    int i    = blockIdx.x * 1024 + tid;
    int lane = tid & 31, wid = tid >> 5;
    int v = (i < NN) ? g_deg_in[i] : 0;

    if (i < NN) {
        int dout = g_deg_out[i]; if (dout < 1) dout = 1;
        int din  = v;            if (din  < 1) din  = 1;
        g_rout[i] = rsqrtf((float)dout);
        g_rin[i]  = rsqrtf((float)din);
    }

    int x = v;
    #pragma unroll
    for (int s = 1; s < 32; s <<= 1) {
        int t = __shfl_up_sync(0xffffffffu, x, s);
        if (lane >= s) x += t;
    }
    if (lane == 31) wsum[wid] = x;
    __syncthreads();
    if (wid == 0) {
        int y = wsum[lane];
        #pragma unroll
        for (int s = 1; s < 32; s <<= 1) {
            int t = __shfl_up_sync(0xffffffffu, y, s);
            if (lane >= s) y += t;
        }
        wsum[lane] = y;
    }
    __syncthreads();

    int excl = x - v + (wid ? wsum[wid - 1] : 0);
    if (i < NN) g_off[i] = excl;
    if (tid == 1023) g_bsum[blockIdx.x] = excl + v;
}

// ---------------- scan pass C ----------------
__global__ void k_scan_c() {
    __shared__ int s_pre;
    int tid = threadIdx.x;
    if (tid == 0) {
        int run = 0;
        #pragma unroll
        for (int b = 0; b < NB; b++) {
            if (b == blockIdx.x) s_pre = run;
            run += g_bsum[b];
        }
        if (blockIdx.x == 0) g_off[NN] = run;
    }
    __syncthreads();
    int i = blockIdx.x * 1024 + tid;
    if (i < NN) {
        int o = g_off[i] + s_pre;
        g_off[i] = o;
        g_cur[i] = o;
    }
}

// ---------------- CSR fill ----------------
__global__ void k_fill(const int* __restrict__ ei) {
    int e = blockIdx.x * blockDim.x + threadIdx.x;
    if (e < EE) {
        int d = ei[EE + e];
        int slot = atomicAdd(&g_cur[d], 1);
        g_srcs[slot] = ei[e];
    }
}

// ---------------- aggA: bufA[i] = rout[i]*rin[i] * sum rout[s]*X[s] ----------
__global__ void k_aggA(const float* __restrict__ X) {
    int t = blockIdx.x * blockDim.x + threadIdx.x;
    int w = t >> 5, lane = t & 31;
    if (w >= NN) return;
    int lo = g_off[w], hi = g_off[w + 1];
    float4 acc = make_float4(0.f, 0.f, 0.f, 0.f);
    for (int j = lo; j < hi; j++) {
        int s = g_srcs[j];
        float r = g_rout[s];
        float4 v = *(const float4*)(X + (size_t)s * DD + lane * 4);
        acc.x = fmaf(r, v.x, acc.x);
        acc.y = fmaf(r, v.y, acc.y);
        acc.z = fmaf(r, v.z, acc.z);
        acc.w = fmaf(r, v.w, acc.w);
    }
    float sc = g_rout[w] * g_rin[w];
    float4 o;
    o.x = acc.x * sc; o.y = acc.y * sc; o.z = acc.z * sc; o.w = acc.w * sc;
    *(float4*)(g_bufA + (size_t)w * DD + lane * 4) = o;
}

// ---------------- aggB: bufB[i] = sum bufA[s] ; srin[i] = rin[i]*sum rout[s] --
__global__ void k_aggB() {
    int t = blockIdx.x * blockDim.x + threadIdx.x;
    int w = t >> 5, lane = t & 31;
    if (w >= NN) return;
    int lo = g_off[w], hi = g_off[w + 1];
    float4 acc = make_float4(0.f, 0.f, 0.f, 0.f);
    float ss = 0.f;
    for (int j = lo; j < hi; j++) {
        int s = g_srcs[j];
        ss += g_rout[s];
        float4 v = *(const float4*)(g_bufA + (size_t)s * DD + lane * 4);
        acc.x += v.x; acc.y += v.y; acc.z += v.z; acc.w += v.w;
    }
    *(float4*)(g_bufB + (size_t)w * DD + lane * 4) = acc;
    if (lane == 0) g_srin[w] = g_rin[w] * ss;
}

// ---------------- helper: stage 64 fp32 rows -> bf16 hi/lo tiles -------------
__device__ __forceinline__ void stage_A(const float* __restrict__ src_base,
                                        int m0, int nmax,
                                        __nv_bfloat16* sAhi, __nv_bfloat16* sAlo,
                                        int tid) {
    int r = tid >> 2, c4 = tid & 3;
    int gi = m0 + r;
    const float4* src = (gi < nmax) ? (const float4*)(src_base + (size_t)gi * DD) : nullptr;
    #pragma unroll
    for (int q = 0; q < 8; q++) {
        int j = c4 + 4 * q;                 // float4 index; cols 4j..4j+3
        float4 v = src ? src[j] : make_float4(0.f, 0.f, 0.f, 0.f);
        BF4 h, l;
        float f[4] = {v.x, v.y, v.z, v.w};
        #pragma unroll
        for (int i = 0; i < 4; i++) {
            h.b[i] = __float2bfloat16(f[i]);
            l.b[i] = __float2bfloat16(f[i] - __bfloat162float(h.b[i]));
        }
        *(ull*)(sAhi + r * APAD + 4 * j) = h.u;
        *(ull*)(sAlo + r * APAD + 4 * j) = l.u;
    }
}

// ---------------- wmma 3-pass mainloop over a 64x128 tile --------------------
// warp (wid): rows 16*(wid&3)..+15, cols 64*(wid>>2)..+63. Result -> sOut.
__device__ __forceinline__ void wmma_tile(const __nv_bfloat16* sAhi,
                                          const __nv_bfloat16* sAlo,
                                          const __nv_bfloat16* sBhi,
                                          const __nv_bfloat16* sBlo,
                                          float* sOut, int wid) {
    int rw = 16 * (wid & 3), cw = 64 * (wid >> 2);
    wmma::fragment<wmma::accumulator, 16, 16, 16, float> acc[4];
    #pragma unroll
    for (int c = 0; c < 4; c++) wmma::fill_fragment(acc[c], 0.f);

    #pragma unroll
    for (int pass = 0; pass < 3; pass++) {
        const __nv_bfloat16* Ap = (pass == 2) ? sAlo : sAhi;
        const __nv_bfloat16* Bp = (pass == 1) ? sBlo : sBhi;
        #pragma unroll
        for (int k = 0; k < 8; k++) {
            wmma::fragment<wmma::matrix_a, 16, 16, 16, __nv_bfloat16, wmma::row_major> af;
            wmma::load_matrix_sync(af, Ap + rw * APAD + k * 16, APAD);
            #pragma unroll
            for (int c = 0; c < 4; c++) {
                wmma::fragment<wmma::matrix_b, 16, 16, 16, __nv_bfloat16, wmma::row_major> bfr;
                wmma::load_matrix_sync(bfr, Bp + (k * 16) * APAD + cw + c * 16, APAD);
                wmma::mma_sync(acc[c], af, bfr, acc[c]);
            }
        }
    }
    __syncthreads();          // all warps done reading sA before overlay write
    #pragma unroll
    for (int c = 0; c < 4; c++)
        wmma::store_matrix_sync(sOut + rw * OPAD + cw + 16 * c, acc[c], OPAD,
                                wmma::mem_row_major);
}

// ---------------- conv (wmma): h2 = rin*(bufB@Wc) + srin*c1 + b2 -> bufA -----
__global__ void __launch_bounds__(256, 2)
k_conv_t(const float* __restrict__ b2) {
    extern __shared__ char smc[];
    __nv_bfloat16* sAhi = (__nv_bfloat16*)smc;
    __nv_bfloat16* sAlo = (__nv_bfloat16*)(smc + A_BYTES);
    __nv_bfloat16* sBhi = (__nv_bfloat16*)(smc + 2 * A_BYTES);
    __nv_bfloat16* sBlo = (__nv_bfloat16*)(smc + 2 * A_BYTES + B_BYTES);
    float*         sOut = (float*)smc;                    // overlays A buffers

    int tid = threadIdx.x, wid = tid >> 5, lane = tid & 31;

    // stage B = Wc hi/lo, once
    #pragma unroll
    for (int q = 0; q < 64; q++) {
        int idx = tid + 256 * q;            // 0..16383
        int k = idx >> 7, n = idx & 127;
        float val = g_Wc[idx];
        __nv_bfloat16 h = __float2bfloat16(val);
        sBhi[k * APAD + n] = h;
        sBlo[k * APAD + n] = __float2bfloat16(val - __bfloat162float(h));
    }
    float4 c1v = *(const float4*)(g_c1 + 4 * lane);
    float4 b2v = *(const float4*)(b2 + 4 * lane);
    __syncthreads();

    for (int tile = blockIdx.x; tile < NT64; tile += 2 * NSM) {
        int m0 = tile * 64;
        __syncthreads();                    // prev epilogue done with sOut
        stage_A(g_bufB, m0, NN, sAhi, sAlo, tid);
        __syncthreads();
        wmma_tile(sAhi, sAlo, sBhi, sBlo, sOut, wid);
        __syncthreads();

        // epilogue: o = out*rin + srin*c1 + b2 -> g_bufA
        #pragma unroll
        for (int q = 0; q < 8; q++) {
            int row = wid * 8 + q;
            int gi = m0 + row;
            if (gi < NN) {
                float ri = g_rin[gi];
                float sr = g_srin[gi];
                const float* rp = sOut + row * OPAD + 4 * lane;
                float4 o;
                o.x = rp[0] * ri + sr * c1v.x + b2v.x;
                o.y = rp[1] * ri + sr * c1v.y + b2v.y;
                o.z = rp[2] * ri + sr * c1v.z + b2v.z;
                o.w = rp[3] * ri + sr * c1v.w + b2v.w;
                *(float4*)(g_bufA + (size_t)gi * DD + 4 * lane) = o;
            }
        }
    }
}

// ---------------- dense (wmma), half-split: bufA -> g_part -------------------
__global__ void __launch_bounds__(256, 2)
k_dense_t(const float* __restrict__ dW,
          const float* __restrict__ db,
          const float* __restrict__ oW) {
    extern __shared__ char smc[];
    __nv_bfloat16* sAhi = (__nv_bfloat16*)smc;
    __nv_bfloat16* sAlo = (__nv_bfloat16*)(smc + A_BYTES);
    __nv_bfloat16* sBhi = (__nv_bfloat16*)(smc + 2 * A_BYTES);
    __nv_bfloat16* sBlo = (__nv_bfloat16*)(smc + 2 * A_BYTES + B_BYTES);
    float*         sOut = (float*)smc;
    __shared__ float s_db[128];
    __shared__ float s_oW[256];

    int tid = threadIdx.x, wid = tid >> 5, lane = tid & 31;
    int half = blockIdx.x & 1;
    int cbase = half * 128;

    // stage this half of dense_W hi/lo, once
    #pragma unroll
    for (int q = 0; q < 64; q++) {
        int idx = tid + 256 * q;
        int k = idx >> 7, n = idx & 127;
        float val = dW[k * UD + cbase + n];
        __nv_bfloat16 h = __float2bfloat16(val);
        sBhi[k * APAD + n] = h;
        sBlo[k * APAD + n] = __float2bfloat16(val - __bfloat162float(h));
    }
    if (tid < 128) {
        s_db[tid]         = db[cbase + tid];
        s_oW[tid * 2]     = oW[(cbase + tid) * 2];
        s_oW[tid * 2 + 1] = oW[(cbase + tid) * 2 + 1];
    }
    __syncthreads();

    for (int tile = blockIdx.x >> 1; tile < NT64; tile += NSM) {
        int m0 = tile * 64;
        __syncthreads();
        stage_A(g_bufA, m0, NN, sAhi, sAlo, tid);
        __syncthreads();
        wmma_tile(sAhi, sAlo, sBhi, sBlo, sOut, wid);
        __syncthreads();

        // epilogue: relu + partial 128->2, warp reduce, write g_part
        #pragma unroll
        for (int q = 0; q < 8; q++) {
            int row = wid * 8 + q;
            const float* rp = sOut + row * OPAD + 4 * lane;
            float p0 = 0.f, p1 = 0.f;
            #pragma unroll
            for (int c = 0; c < 4; c++) {
                int col = 4 * lane + c;
                float v = fmaxf(rp[c] + s_db[col], 0.f);
                p0 = fmaf(v, s_oW[col * 2],     p0);
                p1 = fmaf(v, s_oW[col * 2 + 1], p1);
            }
            #pragma unroll
            for (int o = 16; o; o >>= 1) {
                p0 += __shfl_down_sync(0xffffffffu, p0, o);
                p1 += __shfl_down_sync(0xffffffffu, p1, o);
            }
            if (lane == 0) {
                int gi = m0 + row;
                if (gi < NN)
                    *(float2*)(g_part + (size_t)gi * 4 + half * 2) = make_float2(p0, p1);
            }
        }
    }
}

// ---------------- output: combine halves + ob + softmax + gather -------------
__global__ void k_out(const int* __restrict__ set_idx,
                      const int* __restrict__ oe,
                      const float* __restrict__ ob,
                      float* __restrict__ out) {
    int i = blockIdx.x * blockDim.x + threadIdx.x;
    if (i < NSEL) {
        int node = oe[set_idx[i]];
        float4 pt = *(const float4*)(g_part + (size_t)node * 4);
        float z0 = pt.x + pt.z + ob[0];
        float z1 = pt.y + pt.w + ob[1];
        float m  = fmaxf(z0, z1);
        float e0 = __expf(z0 - m), e1 = __expf(z1 - m);
        float inv = 1.f / (e0 + e1);
        *(float2*)(out + (size_t)i * 2) = make_float2(e0 * inv, e1 * inv);
    }
}

// ---------------- host launch ----------------
extern "C" void kernel_launch(void* const* d_in, const int* in_sizes, int n_in,
                              void* d_out, int out_size) {
    const float* node_state = (const float*)d_in[0];
    const int*   edge_index = (const int*)d_in[1];
    const int*   out_edges  = (const int*)d_in[2];
    const int*   set_idx    = (const int*)d_in[3];
    const float* W1         = (const float*)d_in[4];
    const float* b1         = (const float*)d_in[5];
    const float* W2         = (const float*)d_in[6];
    const float* b2         = (const float*)d_in[7];
    const float* dW         = (const float*)d_in[8];
    const float* db         = (const float*)d_in[9];
    const float* oW         = (const float*)d_in[10];
    const float* ob         = (const float*)d_in[11];
    float* out = (float*)d_out;

    cudaFuncSetAttribute(k_conv_t,  cudaFuncAttributeMaxDynamicSharedMemorySize, GEMM_SMEM_T);
    cudaFuncSetAttribute(k_dense_t, cudaFuncAttributeMaxDynamicSharedMemorySize, GEMM_SMEM_T);

    k_wc     <<<DD + 1, DD>>>(W1, W2, b1);
    k_zero   <<<(NN + 255) / 256, 256>>>();
    k_count  <<<(EE + 255) / 256, 256>>>(edge_index);
    k_scan_a <<<NB, 1024>>>();
    k_scan_c <<<NB, 1024>>>();
    k_fill   <<<(EE + 255) / 256, 256>>>(edge_index);

    k_aggA<<<(NN * 32 + 255) / 256, 256>>>(node_state);
    k_aggB<<<(NN * 32 + 255) / 256, 256>>>();

    k_conv_t <<<2 * NSM, 256, GEMM_SMEM_T>>>(b2);
    k_dense_t<<<2 * NSM, 256, GEMM_SMEM_T>>>(dW, db, oW);
    k_out    <<<(NSEL + 255) / 256, 256>>>(set_idx, out_edges, ob, out);
}

// round 17
// speedup vs baseline: 1.1176x; 1.0396x over previous
#include <cuda_runtime.h>
#include <cuda_bf16.h>
#include <mma.h>

#define NN    50000
#define DD    128
#define EE    600000
#define NPRED 200000
#define NSEL  300000
#define UD    256
#define NB    49
#define NSM   148
#define NT64  ((NN + 63) / 64)   // 782 row-tiles

typedef unsigned long long ull;
using namespace nvcuda;

// ---------------- scratch (device globals: allocation-free) ----------------
__device__ int   g_deg_in[NN];
__device__ int   g_deg_out[NN];
__device__ float g_rin[NN];
__device__ float g_rout[NN];
__device__ int   g_off[NN + 1];
__device__ int   g_cur[NN];
__device__ int   g_srcs[EE];
__device__ int   g_bsum[NB];
__device__ float g_Wc[DD * DD];           // W1 @ W2
__device__ float g_c1[DD];                // b1 @ W2
__device__ float g_srin[NN];
__device__ float g_bufA[(size_t)(NN + 64) * DD];   // +64 rows: unpredicated tile stores
__device__ float g_bufB[(size_t)NN * DD];
__device__ float g_part[(size_t)NN * 4];  // [node][half*2 + {p0,p1}]

union BF4 { __nv_bfloat16 b[4]; ull u; };

// smem geometry for the wmma GEMMs (bf16, padded stride 136 elems = 272B)
#define APAD   136
#define A_BYTES (64 * APAD * 2)            // 17408 per buffer
#define B_BYTES (128 * APAD * 2)           // 34816 per buffer
#define GEMM_SMEM_T (2 * A_BYTES + 2 * B_BYTES)   // 104448
#define OPAD   132                          // f32 epilogue scratch stride

// ---------------- fused zero + combined weights (independent block ranges) ---
// blocks 0..NB-1: zero degree arrays. blocks NB..NB+128: Wc = W1@W2 / c1 = b1@W2.
__global__ void k_zero_wc(const float* __restrict__ W1, const float* __restrict__ W2,
                          const float* __restrict__ b1) {
    int b = blockIdx.x, tid = threadIdx.x;
    if (b < NB) {
        int i = b * 1024 + tid;
        if (i < NN) { g_deg_in[i] = 0; g_deg_out[i] = 0; }
    } else if (tid < DD) {
        int wb = b - NB;                 // 0..128
        int j  = tid;
        const float* a = (wb < DD) ? (W1 + wb * DD) : b1;
        float acc = 0.f;
        #pragma unroll 8
        for (int k = 0; k < DD; k++)
            acc = fmaf(a[k], W2[k * DD + j], acc);
        if (wb < DD) g_Wc[wb * DD + j] = acc;
        else         g_c1[j] = acc;
    }
}

// ---------------- degree counting ----------------
__global__ void k_count(const int* __restrict__ ei) {
    int e = blockIdx.x * blockDim.x + threadIdx.x;
    if (e < EE) {
        atomicAdd(&g_deg_out[ei[e]], 1);
        atomicAdd(&g_deg_in[ei[EE + e]], 1);
    }
}

// ---------------- scan pass A (+ fused rsqrt) ----------------
__global__ void k_scan_a() {
    __shared__ int wsum[32];
    int tid  = threadIdx.x;
    int i    = blockIdx.x * 1024 + tid;
    int lane = tid & 31, wid = tid >> 5;
    int v = (i < NN) ? g_deg_in[i] : 0;

    if (i < NN) {
        int dout = g_deg_out[i]; if (dout < 1) dout = 1;
        int din  = v;            if (din  < 1) din  = 1;
        g_rout[i] = rsqrtf((float)dout);
        g_rin[i]  = rsqrtf((float)din);
    }

    int x = v;
    #pragma unroll
    for (int s = 1; s < 32; s <<= 1) {
        int t = __shfl_up_sync(0xffffffffu, x, s);
        if (lane >= s) x += t;
    }
    if (lane == 31) wsum[wid] = x;
    __syncthreads();
    if (wid == 0) {
        int y = wsum[lane];
        #pragma unroll
        for (int s = 1; s < 32; s <<= 1) {
            int t = __shfl_up_sync(0xffffffffu, y, s);
            if (lane >= s) y += t;
        }
        wsum[lane] = y;
    }
    __syncthreads();

    int excl = x - v + (wid ? wsum[wid - 1] : 0);
    if (i < NN) g_off[i] = excl;
    if (tid == 1023) g_bsum[blockIdx.x] = excl + v;
}

// ---------------- scan pass C ----------------
__global__ void k_scan_c() {
    __shared__ int s_pre;
    int tid = threadIdx.x;
    if (tid == 0) {
        int run = 0;
        #pragma unroll
        for (int b = 0; b < NB; b++) {
            if (b == blockIdx.x) s_pre = run;
            run += g_bsum[b];
        }
        if (blockIdx.x == 0) g_off[NN] = run;
    }
    __syncthreads();
    int i = blockIdx.x * 1024 + tid;
    if (i < NN) {
        int o = g_off[i] + s_pre;
        g_off[i] = o;
        g_cur[i] = o;
    }
}

// ---------------- CSR fill ----------------
__global__ void k_fill(const int* __restrict__ ei) {
    int e = blockIdx.x * blockDim.x + threadIdx.x;
    if (e < EE) {
        int d = ei[EE + e];
        int slot = atomicAdd(&g_cur[d], 1);
        g_srcs[slot] = ei[e];
    }
}

// ---------------- aggA: bufA[i] = rout[i]*rin[i] * sum rout[s]*X[s] ----------
__global__ void k_aggA(const float* __restrict__ X) {
    int t = blockIdx.x * blockDim.x + threadIdx.x;
    int w = t >> 5, lane = t & 31;
    if (w >= NN) return;
    int lo = g_off[w], hi = g_off[w + 1];
    float4 acc = make_float4(0.f, 0.f, 0.f, 0.f);
    for (int j = lo; j < hi; j++) {
        int s = g_srcs[j];
        float r = g_rout[s];
        float4 v = *(const float4*)(X + (size_t)s * DD + lane * 4);
        acc.x = fmaf(r, v.x, acc.x);
        acc.y = fmaf(r, v.y, acc.y);
        acc.z = fmaf(r, v.z, acc.z);
        acc.w = fmaf(r, v.w, acc.w);
    }
    float sc = g_rout[w] * g_rin[w];
    float4 o;
    o.x = acc.x * sc; o.y = acc.y * sc; o.z = acc.z * sc; o.w = acc.w * sc;
    *(float4*)(g_bufA + (size_t)w * DD + lane * 4) = o;
}

// ---------------- aggB: bufB[i] = sum bufA[s] ; srin[i] = rin[i]*sum rout[s] --
__global__ void k_aggB() {
    int t = blockIdx.x * blockDim.x + threadIdx.x;
    int w = t >> 5, lane = t & 31;
    if (w >= NN) return;
    int lo = g_off[w], hi = g_off[w + 1];
    float4 acc = make_float4(0.f, 0.f, 0.f, 0.f);
    float ss = 0.f;
    for (int j = lo; j < hi; j++) {
        int s = g_srcs[j];
        ss += g_rout[s];
        float4 v = *(const float4*)(g_bufA + (size_t)s * DD + lane * 4);
        acc.x += v.x; acc.y += v.y; acc.z += v.z; acc.w += v.w;
    }
    *(float4*)(g_bufB + (size_t)w * DD + lane * 4) = acc;
    if (lane == 0) g_srin[w] = g_rin[w] * ss;
}

// ---------------- helper: stage 64 fp32 rows -> bf16 hi/lo tiles -------------
__device__ __forceinline__ void stage_A(const float* __restrict__ src_base,
                                        int m0, int nmax,
                                        __nv_bfloat16* sAhi, __nv_bfloat16* sAlo,
                                        int tid) {
    int r = tid >> 2, c4 = tid & 3;
    int gi = m0 + r;
    const float4* src = (gi < nmax) ? (const float4*)(src_base + (size_t)gi * DD) : nullptr;
    #pragma unroll
    for (int q = 0; q < 8; q++) {
        int j = c4 + 4 * q;
        float4 v = src ? src[j] : make_float4(0.f, 0.f, 0.f, 0.f);
        BF4 h, l;
        float f[4] = {v.x, v.y, v.z, v.w};
        #pragma unroll
        for (int i = 0; i < 4; i++) {
            h.b[i] = __float2bfloat16(f[i]);
            l.b[i] = __float2bfloat16(f[i] - __bfloat162float(h.b[i]));
        }
        *(ull*)(sAhi + r * APAD + 4 * j) = h.u;
        *(ull*)(sAlo + r * APAD + 4 * j) = l.u;
    }
}

// ---------------- conv (wmma): bufA = raw(bufB@Wc), direct gmem store --------
// affine (rin, srin*c1, b2) is folded into k_dense_t's staging.
__global__ void __launch_bounds__(256, 2)
k_conv_t() {
    extern __shared__ char smc[];
    __nv_bfloat16* sAhi = (__nv_bfloat16*)smc;
    __nv_bfloat16* sAlo = (__nv_bfloat16*)(smc + A_BYTES);
    __nv_bfloat16* sBhi = (__nv_bfloat16*)(smc + 2 * A_BYTES);
    __nv_bfloat16* sBlo = (__nv_bfloat16*)(smc + 2 * A_BYTES + B_BYTES);

    int tid = threadIdx.x, wid = tid >> 5;

    // stage B = Wc hi/lo, once
    #pragma unroll
    for (int q = 0; q < 64; q++) {
        int idx = tid + 256 * q;
        int k = idx >> 7, n = idx & 127;
        float val = g_Wc[idx];
        __nv_bfloat16 h = __float2bfloat16(val);
        sBhi[k * APAD + n] = h;
        sBlo[k * APAD + n] = __float2bfloat16(val - __bfloat162float(h));
    }
    __syncthreads();

    int rw = 16 * (wid & 3), cw = 64 * (wid >> 2);

    for (int tile = blockIdx.x; tile < NT64; tile += 2 * NSM) {
        int m0 = tile * 64;
        __syncthreads();               // prev iter's wmma loads of sA complete
        stage_A(g_bufB, m0, NN, sAhi, sAlo, tid);
        __syncthreads();

        wmma::fragment<wmma::accumulator, 16, 16, 16, float> acc[4];
        #pragma unroll
        for (int c = 0; c < 4; c++) wmma::fill_fragment(acc[c], 0.f);

        #pragma unroll
        for (int pass = 0; pass < 3; pass++) {
            const __nv_bfloat16* Ap = (pass == 2) ? sAlo : sAhi;
            const __nv_bfloat16* Bp = (pass == 1) ? sBlo : sBhi;
            #pragma unroll
            for (int k = 0; k < 8; k++) {
                wmma::fragment<wmma::matrix_a, 16, 16, 16, __nv_bfloat16, wmma::row_major> af;
                wmma::load_matrix_sync(af, Ap + rw * APAD + k * 16, APAD);
                #pragma unroll
                for (int c = 0; c < 4; c++) {
                    wmma::fragment<wmma::matrix_b, 16, 16, 16, __nv_bfloat16, wmma::row_major> bfr;
                    wmma::load_matrix_sync(bfr, Bp + (k * 16) * APAD + cw + c * 16, APAD);
                    wmma::mma_sync(acc[c], af, bfr, acc[c]);
                }
            }
        }

        // direct store: raw result rows m0+rw..+15, cols cw..cw+63 (padded buf)
        #pragma unroll
        for (int c = 0; c < 4; c++)
            wmma::store_matrix_sync(g_bufA + (size_t)(m0 + rw) * DD + cw + 16 * c,
                                    acc[c], DD, wmma::mem_row_major);
    }
}

// ---------------- dense (wmma), half-split: affine(bufA) -> g_part -----------
__global__ void __launch_bounds__(256, 2)
k_dense_t(const float* __restrict__ dW,
          const float* __restrict__ db,
          const float* __restrict__ oW,
          const float* __restrict__ b2) {
    extern __shared__ char smc[];
    __nv_bfloat16* sAhi = (__nv_bfloat16*)smc;
    __nv_bfloat16* sAlo = (__nv_bfloat16*)(smc + A_BYTES);
    __nv_bfloat16* sBhi = (__nv_bfloat16*)(smc + 2 * A_BYTES);
    __nv_bfloat16* sBlo = (__nv_bfloat16*)(smc + 2 * A_BYTES + B_BYTES);
    float*         sOut = (float*)smc;   // overlays A buffers in epilogue
    __shared__ float s_db[128];
    __shared__ float s_oW[256];
    __shared__ float s_c1[DD];
    __shared__ float s_b2[DD];

    int tid = threadIdx.x, wid = tid >> 5, lane = tid & 31;
    int half = blockIdx.x & 1;
    int cbase = half * 128;

    // stage this half of dense_W hi/lo + constants, once
    #pragma unroll
    for (int q = 0; q < 64; q++) {
        int idx = tid + 256 * q;
        int k = idx >> 7, n = idx & 127;
        float val = dW[k * UD + cbase + n];
        __nv_bfloat16 h = __float2bfloat16(val);
        sBhi[k * APAD + n] = h;
        sBlo[k * APAD + n] = __float2bfloat16(val - __bfloat162float(h));
    }
    if (tid < 128) {
        s_db[tid]         = db[cbase + tid];
        s_oW[tid * 2]     = oW[(cbase + tid) * 2];
        s_oW[tid * 2 + 1] = oW[(cbase + tid) * 2 + 1];
        s_c1[tid]         = g_c1[tid];
        s_b2[tid]         = b2[tid];
    }
    __syncthreads();

    int rw = 16 * (wid & 3), cw = 64 * (wid >> 2);

    for (int tile = blockIdx.x >> 1; tile < NT64; tile += NSM) {
        int m0 = tile * 64;
        __syncthreads();               // prev epilogue done with sOut (= sA)

        // stage A: h2 = raw*rin + srin*c1 + b2, split hi/lo
        {
            int r = tid >> 2, c4 = tid & 3;
            int gi = m0 + r;
            bool ok = (gi < NN);
            const float4* src = ok ? (const float4*)(g_bufA + (size_t)gi * DD) : nullptr;
            float ri = ok ? g_rin[gi]  : 0.f;
            float sr = ok ? g_srin[gi] : 0.f;
            #pragma unroll
            for (int q = 0; q < 8; q++) {
                int j = c4 + 4 * q;
                float4 v = ok ? src[j] : make_float4(0.f, 0.f, 0.f, 0.f);
                int col = 4 * j;
                float f[4];
                f[0] = ok ? v.x * ri + sr * s_c1[col]     + s_b2[col]     : 0.f;
                f[1] = ok ? v.y * ri + sr * s_c1[col + 1] + s_b2[col + 1] : 0.f;
                f[2] = ok ? v.z * ri + sr * s_c1[col + 2] + s_b2[col + 2] : 0.f;
                f[3] = ok ? v.w * ri + sr * s_c1[col + 3] + s_b2[col + 3] : 0.f;
                BF4 h, l;
                #pragma unroll
                for (int i = 0; i < 4; i++) {
                    h.b[i] = __float2bfloat16(f[i]);
                    l.b[i] = __float2bfloat16(f[i] - __bfloat162float(h.b[i]));
                }
                *(ull*)(sAhi + r * APAD + 4 * j) = h.u;
                *(ull*)(sAlo + r * APAD + 4 * j) = l.u;
            }
        }
        __syncthreads();

        wmma::fragment<wmma::accumulator, 16, 16, 16, float> acc[4];
        #pragma unroll
        for (int c = 0; c < 4; c++) wmma::fill_fragment(acc[c], 0.f);

        #pragma unroll
        for (int pass = 0; pass < 3; pass++) {
            const __nv_bfloat16* Ap = (pass == 2) ? sAlo : sAhi;
            const __nv_bfloat16* Bp = (pass == 1) ? sBlo : sBhi;
            #pragma unroll
            for (int k = 0; k < 8; k++) {
                wmma::fragment<wmma::matrix_a, 16, 16, 16, __nv_bfloat16, wmma::row_major> af;
                wmma::load_matrix_sync(af, Ap + rw * APAD + k * 16, APAD);
                #pragma unroll
                for (int c = 0; c < 4; c++) {
                    wmma::fragment<wmma::matrix_b, 16, 16, 16, __nv_bfloat16, wmma::row_major> bfr;
                    wmma::load_matrix_sync(bfr, Bp + (k * 16) * APAD + cw + c * 16, APAD);
                    wmma::mma_sync(acc[c], af, bfr, acc[c]);
                }
            }
        }
        __syncthreads();               // all warps done reading sA before overlay
        #pragma unroll
        for (int c = 0; c < 4; c++)
            wmma::store_matrix_sync(sOut + rw * OPAD + cw + 16 * c, acc[c], OPAD,
                                    wmma::mem_row_major);
        __syncthreads();

        // epilogue: relu + partial 128->2, warp reduce, write g_part
        #pragma unroll
        for (int q = 0; q < 8; q++) {
            int row = wid * 8 + q;
            const float* rp = sOut + row * OPAD + 4 * lane;
            float p0 = 0.f, p1 = 0.f;
            #pragma unroll
            for (int c = 0; c < 4; c++) {
                int col = 4 * lane + c;
                float v = fmaxf(rp[c] + s_db[col], 0.f);
                p0 = fmaf(v, s_oW[col * 2],     p0);
                p1 = fmaf(v, s_oW[col * 2 + 1], p1);
            }
            #pragma unroll
            for (int o = 16; o; o >>= 1) {
                p0 += __shfl_down_sync(0xffffffffu, p0, o);
                p1 += __shfl_down_sync(0xffffffffu, p1, o);
            }
            if (lane == 0) {
                int gi = m0 + row;
                if (gi < NN)
                    *(float2*)(g_part + (size_t)gi * 4 + half * 2) = make_float2(p0, p1);
            }
        }
    }
}

// ---------------- output: combine halves + ob + softmax + gather -------------
__global__ void k_out(const int* __restrict__ set_idx,
                      const int* __restrict__ oe,
                      const float* __restrict__ ob,
                      float* __restrict__ out) {
    int i = blockIdx.x * blockDim.x + threadIdx.x;
    if (i < NSEL) {
        int node = oe[set_idx[i]];
        float4 pt = *(const float4*)(g_part + (size_t)node * 4);
        float z0 = pt.x + pt.z + ob[0];
        float z1 = pt.y + pt.w + ob[1];
        float m  = fmaxf(z0, z1);
        float e0 = __expf(z0 - m), e1 = __expf(z1 - m);
        float inv = 1.f / (e0 + e1);
        *(float2*)(out + (size_t)i * 2) = make_float2(e0 * inv, e1 * inv);
    }
}

// ---------------- host launch ----------------
extern "C" void kernel_launch(void* const* d_in, const int* in_sizes, int n_in,
                              void* d_out, int out_size) {
    const float* node_state = (const float*)d_in[0];
    const int*   edge_index = (const int*)d_in[1];
    const int*   out_edges  = (const int*)d_in[2];
    const int*   set_idx    = (const int*)d_in[3];
    const float* W1         = (const float*)d_in[4];
    const float* b1         = (const float*)d_in[5];
    const float* W2         = (const float*)d_in[6];
    const float* b2         = (const float*)d_in[7];
    const float* dW         = (const float*)d_in[8];
    const float* db         = (const float*)d_in[9];
    const float* oW         = (const float*)d_in[10];
    const float* ob         = (const float*)d_in[11];
    float* out = (float*)d_out;

    cudaFuncSetAttribute(k_conv_t,  cudaFuncAttributeMaxDynamicSharedMemorySize, GEMM_SMEM_T);
    cudaFuncSetAttribute(k_dense_t, cudaFuncAttributeMaxDynamicSharedMemorySize, GEMM_SMEM_T);

    k_zero_wc<<<NB + DD + 1, 1024>>>(W1, W2, b1);
    k_count  <<<(EE + 255) / 256, 256>>>(edge_index);
    k_scan_a <<<NB, 1024>>>();
    k_scan_c <<<NB, 1024>>>();
    k_fill   <<<(EE + 255) / 256, 256>>>(edge_index);

    k_aggA<<<(NN * 32 + 255) / 256, 256>>>(node_state);
    k_aggB<<<(NN * 32 + 255) / 256, 256>>>();

    k_conv_t <<<2 * NSM, 256, GEMM_SMEM_T>>>();
    k_dense_t<<<2 * NSM, 256, GEMM_SMEM_T>>>(dW, db, oW, b2);
    k_out    <<<(NSEL + 255) / 256, 256>>>(set_idx, out_edges, ob, out);
}